// round 11
// baseline (speedup 1.0000x reference)
#include <cuda_runtime.h>
#include <cuda_fp16.h>
#include <mma.h>

using namespace nvcuda;

// Problem constants
#define N_NODES 50000
#define N_EDGES 800000
#define IN_F    128
#define OUT_F   64
#define NBLK_SCAN 196            // ceil(50000/256)

// ---------------------------------------------------------------------------
// Device scratch (no allocations allowed)
// ---------------------------------------------------------------------------
__device__ int    g_row_cnt[N_NODES];          // histogram, then scatter cursor
__device__ int    g_row_ptr[N_NODES + 1];      // CSR row pointers
__device__ int    g_part[NBLK_SCAN];           // per-block partial sums
__device__ int2   g_edge_sorted[N_EDGES];      // packed (col*16, attr-bits fp32)
__device__ __half g_h0[N_NODES * OUT_F];       // ping (fp16 features)
__device__ __half g_h1[N_NODES * OUT_F];       // pong (fp16 features)

// ---------------------------------------------------------------------------
// histogram of destination rows; 1 edge/thread
// ---------------------------------------------------------------------------
__global__ void hist_kernel(const int* __restrict__ ei) {
    int e = blockIdx.x * blockDim.x + threadIdx.x;
    if (e < N_EDGES) atomicAdd(&g_row_cnt[ei[e]], 1);
}

// ---------------------------------------------------------------------------
// scan phase 1: per-block (256 counters) partial sums  [196 blocks]
// ---------------------------------------------------------------------------
__global__ void scan_partial_kernel() {
    __shared__ int sm[256];
    int t = threadIdx.x;
    int i = blockIdx.x * 256 + t;
    sm[t] = (i < N_NODES) ? g_row_cnt[i] : 0;
    __syncthreads();
#pragma unroll
    for (int off = 128; off > 0; off >>= 1) {
        if (t < off) sm[t] += sm[t + off];
        __syncthreads();
    }
    if (t == 0) g_part[blockIdx.x] = sm[0];
}

// ---------------------------------------------------------------------------
// scan phase 2 (fused): block offset = masked reduction over partials,
// plus local exclusive scan -> row_ptr & scatter cursor.  [196 blocks]
// ---------------------------------------------------------------------------
__global__ void scan_apply_kernel() {
    __shared__ int sm[256];
    __shared__ int po[256];
    int t   = threadIdx.x;
    int bid = blockIdx.x;
    int i   = bid * 256 + t;

    po[t] = (t < bid && t < NBLK_SCAN) ? g_part[t] : 0;
    int c = (i < N_NODES) ? g_row_cnt[i] : 0;
    sm[t] = c;
    __syncthreads();

#pragma unroll
    for (int off = 128; off > 0; off >>= 1) {
        if (t < off) po[t] += po[t + off];
        __syncthreads();
    }
    int blk_off = po[0];

    int v = c;
    for (int off = 1; off < 256; off <<= 1) {
        int add = (t >= off) ? sm[t - off] : 0;
        __syncthreads();
        v += add;
        sm[t] = v;
        __syncthreads();
    }
    int excl = v - c + blk_off;
    if (i < N_NODES) {
        g_row_ptr[i] = excl;
        g_row_cnt[i] = excl;   // scatter cursor
    }
    if (bid == 0 && t == 0) g_row_ptr[N_NODES] = N_EDGES;
}

// ---------------------------------------------------------------------------
// scatter edges into CSR order; 1 edge/thread.
// Stores col pre-scaled by 16 (uint2 index) to save an IMAD in spmm.
// ---------------------------------------------------------------------------
__global__ void scatter_kernel(const int* __restrict__ ei,
                               const float* __restrict__ attr) {
    int e = blockIdx.x * blockDim.x + threadIdx.x;
    if (e < N_EDGES) {
        int row = ei[e];
        int col = ei[N_EDGES + e];
        float a = attr[e];
        int pos = atomicAdd(&g_row_cnt[row], 1);
        g_edge_sorted[pos] = make_int2(col * 16, __float_as_int(a));
    }
}

// ---------------------------------------------------------------------------
// GEMM via tensor cores: out[n,o] = sum_k x[n,k] * W[o,k] + b[o]
// fp16 inputs (converted on the fly), fp32 accumulate, fp16 store.
// ---------------------------------------------------------------------------
__global__ __launch_bounds__(128)
void gemm_wmma_kernel(const float* __restrict__ x,
                      const float* __restrict__ W,
                      const float* __restrict__ b,
                      __half* __restrict__ out) {
    __shared__ __half Xs[64 * 128];
    __shared__ __half Wsh[64 * 128];

    int tid  = threadIdx.x;
    int warp = tid >> 5;
    int lane = tid & 31;
    int row0 = blockIdx.x * 64;

    for (int i = tid; i < 64 * 128 / 4; i += 128) {
        float4 v = __ldg((const float4*)W + i);
        __half2 h0 = __floats2half2_rn(v.x, v.y);
        __half2 h1 = __floats2half2_rn(v.z, v.w);
        ((__half2*)Wsh)[i * 2]     = h0;
        ((__half2*)Wsh)[i * 2 + 1] = h1;
    }
    for (int i = tid; i < 64 * 128 / 4; i += 128) {
        int r = i >> 5;
        int c = i & 31;
        int gr = row0 + r;
        if (gr >= N_NODES) gr = N_NODES - 1;
        float4 v = __ldg((const float4*)&x[gr * IN_F] + c);
        __half2 h0 = __floats2half2_rn(v.x, v.y);
        __half2 h1 = __floats2half2_rn(v.z, v.w);
        ((__half2*)Xs)[i * 2]     = h0;
        ((__half2*)Xs)[i * 2 + 1] = h1;
    }
    __syncthreads();

    wmma::fragment<wmma::accumulator, 16, 16, 16, float> acc[4];
#pragma unroll
    for (int j = 0; j < 4; j++) wmma::fill_fragment(acc[j], 0.0f);

#pragma unroll
    for (int k = 0; k < IN_F; k += 16) {
        wmma::fragment<wmma::matrix_a, 16, 16, 16, __half, wmma::row_major> af;
        wmma::load_matrix_sync(af, Xs + (warp * 16) * 128 + k, 128);
#pragma unroll
        for (int j = 0; j < 4; j++) {
            wmma::fragment<wmma::matrix_b, 16, 16, 16, __half, wmma::col_major> bf;
            wmma::load_matrix_sync(bf, Wsh + (j * 16) * 128 + k, 128);
            wmma::mma_sync(acc[j], af, bf, acc[j]);
        }
    }

    __syncthreads();
    float* stage = (float*)Xs;
    float* st = stage + warp * 16 * 64;
#pragma unroll
    for (int j = 0; j < 4; j++)
        wmma::store_matrix_sync(st + j * 16, acc[j], 64, wmma::mem_row_major);
    __syncwarp();

    for (int it = lane; it < 16 * 16; it += 32) {
        int r  = it >> 4;
        int c4 = it & 15;
        int gr = row0 + warp * 16 + r;
        if (gr < N_NODES) {
            float4 bias = __ldg((const float4*)b + c4);
            float v0 = st[r * 64 + c4 * 4 + 0] + bias.x;
            float v1 = st[r * 64 + c4 * 4 + 1] + bias.y;
            float v2 = st[r * 64 + c4 * 4 + 2] + bias.z;
            float v3 = st[r * 64 + c4 * 4 + 3] + bias.w;
            __half2 h0 = __floats2half2_rn(v0, v1);
            __half2 h1 = __floats2half2_rn(v2, v3);
            uint2 u;
            u.x = *(unsigned int*)&h0;
            u.y = *(unsigned int*)&h1;
            ((uint2*)out)[gr * 16 + c4] = u;
        }
    }
}

// ---------------------------------------------------------------------------
// SPMM (CSR): 2 rows/warp, 16 lanes/row, 4 fp16 feats per lane (8B gather).
// fp32 accumulate, unroll-4 with SOFTWARE-PIPELINED edge-meta prefetch:
// the next batch's 4 metas are loaded before the current batch's FMAs,
// overlapping meta latency with gather latency.
// FINAL=true writes fp32 to d_out, else fp16.
// ---------------------------------------------------------------------------
template <bool FINAL>
__global__ __launch_bounds__(256, 8)
void spmm_kernel(const __half* __restrict__ in, void* __restrict__ outv) {
    int warp = (blockIdx.x * blockDim.x + threadIdx.x) >> 5;
    int lane = threadIdx.x & 31;
    int half_id = lane >> 4;
    int fl      = lane & 15;

    int row = warp * 2 + half_id;
    if (row >= N_NODES) return;

    int s = __ldg(&g_row_ptr[row]);
    int e = __ldg(&g_row_ptr[row + 1]);

    const uint2* inp = (const uint2*)in;
    float4 a0 = make_float4(0.f, 0.f, 0.f, 0.f);
    float4 a1 = make_float4(0.f, 0.f, 0.f, 0.f);
    float4 a2 = make_float4(0.f, 0.f, 0.f, 0.f);
    float4 a3 = make_float4(0.f, 0.f, 0.f, 0.f);

    int i = s;
    int2 m0, m1, m2, m3;
    bool have = (i + 4 <= e);
    if (have) {
        m0 = __ldg(&g_edge_sorted[i]);
        m1 = __ldg(&g_edge_sorted[i + 1]);
        m2 = __ldg(&g_edge_sorted[i + 2]);
        m3 = __ldg(&g_edge_sorted[i + 3]);
    }

    // pipelined main loop: gathers for current metas, prefetch next metas,
    // then FMAs — meta latency hides under gather latency.
    for (; i + 8 <= e; i += 4) {
        uint2 v0 = __ldg(&inp[m0.x + fl]);
        uint2 v1 = __ldg(&inp[m1.x + fl]);
        uint2 v2 = __ldg(&inp[m2.x + fl]);
        uint2 v3 = __ldg(&inp[m3.x + fl]);

        int2 n0 = __ldg(&g_edge_sorted[i + 4]);
        int2 n1 = __ldg(&g_edge_sorted[i + 5]);
        int2 n2 = __ldg(&g_edge_sorted[i + 6]);
        int2 n3 = __ldg(&g_edge_sorted[i + 7]);

        float w0 = __int_as_float(m0.y);
        float w1 = __int_as_float(m1.y);
        float w2 = __int_as_float(m2.y);
        float w3 = __int_as_float(m3.y);

        float2 f;
        f = __half22float2(*(__half2*)&v0.x); a0.x += w0 * f.x; a0.y += w0 * f.y;
        f = __half22float2(*(__half2*)&v0.y); a0.z += w0 * f.x; a0.w += w0 * f.y;
        f = __half22float2(*(__half2*)&v1.x); a1.x += w1 * f.x; a1.y += w1 * f.y;
        f = __half22float2(*(__half2*)&v1.y); a1.z += w1 * f.x; a1.w += w1 * f.y;
        f = __half22float2(*(__half2*)&v2.x); a2.x += w2 * f.x; a2.y += w2 * f.y;
        f = __half22float2(*(__half2*)&v2.y); a2.z += w2 * f.x; a2.w += w2 * f.y;
        f = __half22float2(*(__half2*)&v3.x); a3.x += w3 * f.x; a3.y += w3 * f.y;
        f = __half22float2(*(__half2*)&v3.y); a3.z += w3 * f.x; a3.w += w3 * f.y;

        m0 = n0; m1 = n1; m2 = n2; m3 = n3;
    }

    // drain the last full batch (metas already in m0..m3)
    if (have && i + 4 <= e) {
        uint2 v0 = __ldg(&inp[m0.x + fl]);
        uint2 v1 = __ldg(&inp[m1.x + fl]);
        uint2 v2 = __ldg(&inp[m2.x + fl]);
        uint2 v3 = __ldg(&inp[m3.x + fl]);
        float w0 = __int_as_float(m0.y);
        float w1 = __int_as_float(m1.y);
        float w2 = __int_as_float(m2.y);
        float w3 = __int_as_float(m3.y);
        float2 f;
        f = __half22float2(*(__half2*)&v0.x); a0.x += w0 * f.x; a0.y += w0 * f.y;
        f = __half22float2(*(__half2*)&v0.y); a0.z += w0 * f.x; a0.w += w0 * f.y;
        f = __half22float2(*(__half2*)&v1.x); a1.x += w1 * f.x; a1.y += w1 * f.y;
        f = __half22float2(*(__half2*)&v1.y); a1.z += w1 * f.x; a1.w += w1 * f.y;
        f = __half22float2(*(__half2*)&v2.x); a2.x += w2 * f.x; a2.y += w2 * f.y;
        f = __half22float2(*(__half2*)&v2.y); a2.z += w2 * f.x; a2.w += w2 * f.y;
        f = __half22float2(*(__half2*)&v3.x); a3.x += w3 * f.x; a3.y += w3 * f.y;
        f = __half22float2(*(__half2*)&v3.y); a3.z += w3 * f.x; a3.w += w3 * f.y;
        i += 4;
    }

    // scalar tail
    for (; i < e; i++) {
        int2 ed = __ldg(&g_edge_sorted[i]);
        uint2 v = __ldg(&inp[ed.x + fl]);
        float w = __int_as_float(ed.y);
        float2 f;
        f = __half22float2(*(__half2*)&v.x); a0.x += w * f.x; a0.y += w * f.y;
        f = __half22float2(*(__half2*)&v.y); a0.z += w * f.x; a0.w += w * f.y;
    }

    float4 acc;
    acc.x = (a0.x + a1.x) + (a2.x + a3.x);
    acc.y = (a0.y + a1.y) + (a2.y + a3.y);
    acc.z = (a0.z + a1.z) + (a2.z + a3.z);
    acc.w = (a0.w + a1.w) + (a2.w + a3.w);

    if (FINAL) {
        ((float4*)outv)[row * 16 + fl] = acc;
    } else {
        __half2 h0 = __floats2half2_rn(acc.x, acc.y);
        __half2 h1 = __floats2half2_rn(acc.z, acc.w);
        uint2 st;
        st.x = *(unsigned int*)&h0;
        st.y = *(unsigned int*)&h1;
        ((uint2*)outv)[row * 16 + fl] = st;
    }
}

// ---------------------------------------------------------------------------
// launch: fork GEMM onto a side stream, overlapping with CSR build
// ---------------------------------------------------------------------------
extern "C" void kernel_launch(void* const* d_in, const int* in_sizes, int n_in,
                              void* d_out, int out_size) {
    const float* x    = (const float*)d_in[0];
    const int*   ei   = (const int*)d_in[1];   // int32 (JAX x64 disabled)
    const float* attr = (const float*)d_in[2];
    const float* W    = (const float*)d_in[3];
    const float* b    = (const float*)d_in[4];
    float*       out  = (float*)d_out;

    __half *h0, *h1;
    int    *cnt;
    cudaGetSymbolAddress((void**)&h0,  g_h0);
    cudaGetSymbolAddress((void**)&h1,  g_h1);
    cudaGetSymbolAddress((void**)&cnt, g_row_cnt);

    // Fork side stream for the independent GEMM.
    cudaStream_t s2;
    cudaStreamCreateWithFlags(&s2, cudaStreamNonBlocking);
    cudaEvent_t ev_fork, ev_join;
    cudaEventCreateWithFlags(&ev_fork, cudaEventDisableTiming);
    cudaEventCreateWithFlags(&ev_join, cudaEventDisableTiming);

    cudaEventRecord(ev_fork, 0);
    cudaStreamWaitEvent(s2, ev_fork, 0);

    gemm_wmma_kernel<<<(N_NODES + 63) / 64, 128, 0, s2>>>(x, W, b, h0);
    cudaEventRecord(ev_join, s2);

    // Main stream: CSR build (scan = 2 full-chip phases)
    cudaMemsetAsync(cnt, 0, N_NODES * sizeof(int), 0);
    hist_kernel<<<(N_EDGES + 255) / 256, 256>>>(ei);
    scan_partial_kernel<<<NBLK_SCAN, 256>>>();
    scan_apply_kernel<<<NBLK_SCAN, 256>>>();
    scatter_kernel<<<(N_EDGES + 255) / 256, 256>>>(ei, attr);

    cudaStreamWaitEvent(0, ev_join, 0);

    // 3 SPMM rounds: h0 -> h1 -> h0 -> d_out (fp32); 2 rows per warp
    int blocks = (N_NODES / 2 * 32 + 255) / 256;
    spmm_kernel<false><<<blocks, 256>>>(h0, h1);
    spmm_kernel<false><<<blocks, 256>>>(h1, h0);
    spmm_kernel<true ><<<blocks, 256>>>(h0, out);
}

// round 12
// speedup vs baseline: 1.2429x; 1.2429x over previous
#include <cuda_runtime.h>
#include <cuda_fp16.h>
#include <mma.h>

using namespace nvcuda;

// Problem constants
#define N_NODES 50000
#define N_EDGES 800000
#define IN_F    128
#define OUT_F   64
#define NBLK_SCAN 196            // ceil(50000/256)

// ---------------------------------------------------------------------------
// Device scratch (no allocations allowed)
// ---------------------------------------------------------------------------
__device__ int    g_row_cnt[N_NODES];          // histogram, then scatter cursor
__device__ int    g_row_ptr[N_NODES + 1];      // CSR row pointers
__device__ int    g_part[NBLK_SCAN];           // per-block partial sums
__device__ int2   g_edge_sorted[N_EDGES];      // packed (col*16, attr-bits fp32)
__device__ __half g_h0[N_NODES * OUT_F];       // ping (fp16 features)
__device__ __half g_h1[N_NODES * OUT_F];       // pong (fp16 features)

// ---------------------------------------------------------------------------
// histogram of destination rows; 1 edge/thread
// ---------------------------------------------------------------------------
__global__ void hist_kernel(const int* __restrict__ ei) {
    int e = blockIdx.x * blockDim.x + threadIdx.x;
    if (e < N_EDGES) atomicAdd(&g_row_cnt[ei[e]], 1);
}

// ---------------------------------------------------------------------------
// scan phase 1: per-block (256 counters) partial sums  [196 blocks]
// ---------------------------------------------------------------------------
__global__ void scan_partial_kernel() {
    __shared__ int sm[256];
    int t = threadIdx.x;
    int i = blockIdx.x * 256 + t;
    sm[t] = (i < N_NODES) ? g_row_cnt[i] : 0;
    __syncthreads();
#pragma unroll
    for (int off = 128; off > 0; off >>= 1) {
        if (t < off) sm[t] += sm[t + off];
        __syncthreads();
    }
    if (t == 0) g_part[blockIdx.x] = sm[0];
}

// ---------------------------------------------------------------------------
// scan phase 2 (fused): block offset = masked reduction over partials,
// plus local exclusive scan -> row_ptr & scatter cursor.  [196 blocks]
// ---------------------------------------------------------------------------
__global__ void scan_apply_kernel() {
    __shared__ int sm[256];
    __shared__ int po[256];
    int t   = threadIdx.x;
    int bid = blockIdx.x;
    int i   = bid * 256 + t;

    po[t] = (t < bid && t < NBLK_SCAN) ? g_part[t] : 0;
    int c = (i < N_NODES) ? g_row_cnt[i] : 0;
    sm[t] = c;
    __syncthreads();

#pragma unroll
    for (int off = 128; off > 0; off >>= 1) {
        if (t < off) po[t] += po[t + off];
        __syncthreads();
    }
    int blk_off = po[0];

    int v = c;
    for (int off = 1; off < 256; off <<= 1) {
        int add = (t >= off) ? sm[t - off] : 0;
        __syncthreads();
        v += add;
        sm[t] = v;
        __syncthreads();
    }
    int excl = v - c + blk_off;
    if (i < N_NODES) {
        g_row_ptr[i] = excl;
        g_row_cnt[i] = excl;   // scatter cursor
    }
    if (bid == 0 && t == 0) g_row_ptr[N_NODES] = N_EDGES;
}

// ---------------------------------------------------------------------------
// scatter edges into CSR order; 1 edge/thread.
// Stores col pre-scaled by 16 (uint2 index) to save an IMAD in spmm.
// ---------------------------------------------------------------------------
__global__ void scatter_kernel(const int* __restrict__ ei,
                               const float* __restrict__ attr) {
    int e = blockIdx.x * blockDim.x + threadIdx.x;
    if (e < N_EDGES) {
        int row = ei[e];
        int col = ei[N_EDGES + e];
        float a = attr[e];
        int pos = atomicAdd(&g_row_cnt[row], 1);
        g_edge_sorted[pos] = make_int2(col * 16, __float_as_int(a));
    }
}

// ---------------------------------------------------------------------------
// GEMM via tensor cores: out[n,o] = sum_k x[n,k] * W[o,k] + b[o]
// fp16 inputs (converted on the fly), fp32 accumulate, fp16 store.
// ---------------------------------------------------------------------------
__global__ __launch_bounds__(128)
void gemm_wmma_kernel(const float* __restrict__ x,
                      const float* __restrict__ W,
                      const float* __restrict__ b,
                      __half* __restrict__ out) {
    __shared__ __half Xs[64 * 128];
    __shared__ __half Wsh[64 * 128];

    int tid  = threadIdx.x;
    int warp = tid >> 5;
    int lane = tid & 31;
    int row0 = blockIdx.x * 64;

    for (int i = tid; i < 64 * 128 / 4; i += 128) {
        float4 v = __ldg((const float4*)W + i);
        __half2 h0 = __floats2half2_rn(v.x, v.y);
        __half2 h1 = __floats2half2_rn(v.z, v.w);
        ((__half2*)Wsh)[i * 2]     = h0;
        ((__half2*)Wsh)[i * 2 + 1] = h1;
    }
    for (int i = tid; i < 64 * 128 / 4; i += 128) {
        int r = i >> 5;
        int c = i & 31;
        int gr = row0 + r;
        if (gr >= N_NODES) gr = N_NODES - 1;
        float4 v = __ldg((const float4*)&x[gr * IN_F] + c);
        __half2 h0 = __floats2half2_rn(v.x, v.y);
        __half2 h1 = __floats2half2_rn(v.z, v.w);
        ((__half2*)Xs)[i * 2]     = h0;
        ((__half2*)Xs)[i * 2 + 1] = h1;
    }
    __syncthreads();

    wmma::fragment<wmma::accumulator, 16, 16, 16, float> acc[4];
#pragma unroll
    for (int j = 0; j < 4; j++) wmma::fill_fragment(acc[j], 0.0f);

#pragma unroll
    for (int k = 0; k < IN_F; k += 16) {
        wmma::fragment<wmma::matrix_a, 16, 16, 16, __half, wmma::row_major> af;
        wmma::load_matrix_sync(af, Xs + (warp * 16) * 128 + k, 128);
#pragma unroll
        for (int j = 0; j < 4; j++) {
            wmma::fragment<wmma::matrix_b, 16, 16, 16, __half, wmma::col_major> bf;
            wmma::load_matrix_sync(bf, Wsh + (j * 16) * 128 + k, 128);
            wmma::mma_sync(acc[j], af, bf, acc[j]);
        }
    }

    __syncthreads();
    float* stage = (float*)Xs;
    float* st = stage + warp * 16 * 64;
#pragma unroll
    for (int j = 0; j < 4; j++)
        wmma::store_matrix_sync(st + j * 16, acc[j], 64, wmma::mem_row_major);
    __syncwarp();

    for (int it = lane; it < 16 * 16; it += 32) {
        int r  = it >> 4;
        int c4 = it & 15;
        int gr = row0 + warp * 16 + r;
        if (gr < N_NODES) {
            float4 bias = __ldg((const float4*)b + c4);
            float v0 = st[r * 64 + c4 * 4 + 0] + bias.x;
            float v1 = st[r * 64 + c4 * 4 + 1] + bias.y;
            float v2 = st[r * 64 + c4 * 4 + 2] + bias.z;
            float v3 = st[r * 64 + c4 * 4 + 3] + bias.w;
            __half2 h0 = __floats2half2_rn(v0, v1);
            __half2 h1 = __floats2half2_rn(v2, v3);
            uint2 u;
            u.x = *(unsigned int*)&h0;
            u.y = *(unsigned int*)&h1;
            ((uint2*)out)[gr * 16 + c4] = u;
        }
    }
}

// ---------------------------------------------------------------------------
// SPMM (CSR): 2 rows/warp, 16 lanes/row, 4 fp16 feats per lane (8B gather).
// fp32 accumulate, unroll-4. FINAL=true writes fp32 to d_out, else fp16.
// Edge payload carries col*16 (pre-scaled uint2 index).
// (Frozen: measured-best configuration, R7/R9 = 107.8/106.5 us.)
// ---------------------------------------------------------------------------
template <bool FINAL>
__global__ __launch_bounds__(256, 8)
void spmm_kernel(const __half* __restrict__ in, void* __restrict__ outv) {
    int warp = (blockIdx.x * blockDim.x + threadIdx.x) >> 5;
    int lane = threadIdx.x & 31;
    int half_id = lane >> 4;
    int fl      = lane & 15;

    int row = warp * 2 + half_id;
    if (row >= N_NODES) return;

    int s = __ldg(&g_row_ptr[row]);
    int e = __ldg(&g_row_ptr[row + 1]);

    const uint2* inp = (const uint2*)in;
    float4 a0 = make_float4(0.f, 0.f, 0.f, 0.f);
    float4 a1 = make_float4(0.f, 0.f, 0.f, 0.f);
    float4 a2 = make_float4(0.f, 0.f, 0.f, 0.f);
    float4 a3 = make_float4(0.f, 0.f, 0.f, 0.f);

    int i = s;
    for (; i + 4 <= e; i += 4) {
        int2 e0 = __ldg(&g_edge_sorted[i]);
        int2 e1 = __ldg(&g_edge_sorted[i + 1]);
        int2 e2 = __ldg(&g_edge_sorted[i + 2]);
        int2 e3 = __ldg(&g_edge_sorted[i + 3]);
        uint2 v0 = __ldg(&inp[e0.x + fl]);
        uint2 v1 = __ldg(&inp[e1.x + fl]);
        uint2 v2 = __ldg(&inp[e2.x + fl]);
        uint2 v3 = __ldg(&inp[e3.x + fl]);
        float w0 = __int_as_float(e0.y);
        float w1 = __int_as_float(e1.y);
        float w2 = __int_as_float(e2.y);
        float w3 = __int_as_float(e3.y);

        float2 f;
        f = __half22float2(*(__half2*)&v0.x); a0.x += w0 * f.x; a0.y += w0 * f.y;
        f = __half22float2(*(__half2*)&v0.y); a0.z += w0 * f.x; a0.w += w0 * f.y;
        f = __half22float2(*(__half2*)&v1.x); a1.x += w1 * f.x; a1.y += w1 * f.y;
        f = __half22float2(*(__half2*)&v1.y); a1.z += w1 * f.x; a1.w += w1 * f.y;
        f = __half22float2(*(__half2*)&v2.x); a2.x += w2 * f.x; a2.y += w2 * f.y;
        f = __half22float2(*(__half2*)&v2.y); a2.z += w2 * f.x; a2.w += w2 * f.y;
        f = __half22float2(*(__half2*)&v3.x); a3.x += w3 * f.x; a3.y += w3 * f.y;
        f = __half22float2(*(__half2*)&v3.y); a3.z += w3 * f.x; a3.w += w3 * f.y;
    }
    for (; i < e; i++) {
        int2 ed = __ldg(&g_edge_sorted[i]);
        uint2 v = __ldg(&inp[ed.x + fl]);
        float w = __int_as_float(ed.y);
        float2 f;
        f = __half22float2(*(__half2*)&v.x); a0.x += w * f.x; a0.y += w * f.y;
        f = __half22float2(*(__half2*)&v.y); a0.z += w * f.x; a0.w += w * f.y;
    }

    float4 acc;
    acc.x = (a0.x + a1.x) + (a2.x + a3.x);
    acc.y = (a0.y + a1.y) + (a2.y + a3.y);
    acc.z = (a0.z + a1.z) + (a2.z + a3.z);
    acc.w = (a0.w + a1.w) + (a2.w + a3.w);

    if (FINAL) {
        ((float4*)outv)[row * 16 + fl] = acc;
    } else {
        __half2 h0 = __floats2half2_rn(acc.x, acc.y);
        __half2 h1 = __floats2half2_rn(acc.z, acc.w);
        uint2 st;
        st.x = *(unsigned int*)&h0;
        st.y = *(unsigned int*)&h1;
        ((uint2*)outv)[row * 16 + fl] = st;
    }
}

// ---------------------------------------------------------------------------
// launch: fork GEMM onto a side stream, overlapping with CSR build
// ---------------------------------------------------------------------------
extern "C" void kernel_launch(void* const* d_in, const int* in_sizes, int n_in,
                              void* d_out, int out_size) {
    const float* x    = (const float*)d_in[0];
    const int*   ei   = (const int*)d_in[1];   // int32 (JAX x64 disabled)
    const float* attr = (const float*)d_in[2];
    const float* W    = (const float*)d_in[3];
    const float* b    = (const float*)d_in[4];
    float*       out  = (float*)d_out;

    __half *h0, *h1;
    int    *cnt;
    cudaGetSymbolAddress((void**)&h0,  g_h0);
    cudaGetSymbolAddress((void**)&h1,  g_h1);
    cudaGetSymbolAddress((void**)&cnt, g_row_cnt);

    // Fork side stream for the independent GEMM.
    cudaStream_t s2;
    cudaStreamCreateWithFlags(&s2, cudaStreamNonBlocking);
    cudaEvent_t ev_fork, ev_join;
    cudaEventCreateWithFlags(&ev_fork, cudaEventDisableTiming);
    cudaEventCreateWithFlags(&ev_join, cudaEventDisableTiming);

    cudaEventRecord(ev_fork, 0);
    cudaStreamWaitEvent(s2, ev_fork, 0);

    gemm_wmma_kernel<<<(N_NODES + 63) / 64, 128, 0, s2>>>(x, W, b, h0);
    cudaEventRecord(ev_join, s2);

    // Main stream: CSR build (scan = 2 full-chip phases)
    cudaMemsetAsync(cnt, 0, N_NODES * sizeof(int), 0);
    hist_kernel<<<(N_EDGES + 255) / 256, 256>>>(ei);
    scan_partial_kernel<<<NBLK_SCAN, 256>>>();
    scan_apply_kernel<<<NBLK_SCAN, 256>>>();
    scatter_kernel<<<(N_EDGES + 255) / 256, 256>>>(ei, attr);

    cudaStreamWaitEvent(0, ev_join, 0);

    // 3 SPMM rounds: h0 -> h1 -> h0 -> d_out (fp32); 2 rows per warp
    int blocks = (N_NODES / 2 * 32 + 255) / 256;
    spmm_kernel<false><<<blocks, 256>>>(h0, h1);
    spmm_kernel<false><<<blocks, 256>>>(h1, h0);
    spmm_kernel<true ><<<blocks, 256>>>(h0, out);
}

// round 13
// speedup vs baseline: 1.2634x; 1.0165x over previous
#include <cuda_runtime.h>
#include <cuda_fp16.h>
#include <mma.h>

using namespace nvcuda;

// Problem constants
#define N_NODES 50000
#define N_EDGES 800000
#define IN_F    128
#define OUT_F   64
#define NBLK_SCAN 196            // ceil(50000/256)

// ---------------------------------------------------------------------------
// Device scratch (no allocations allowed)
// ---------------------------------------------------------------------------
__device__ int    g_row_cnt[N_NODES];          // histogram, then scatter cursor
__device__ int    g_row_ptr[N_NODES + 1];      // CSR row pointers
__device__ int    g_part[NBLK_SCAN];           // per-block partial sums
__device__ int2   g_edge_sorted[N_EDGES];      // packed (col*16, attr-bits fp32)
__device__ __half g_h0[N_NODES * OUT_F];       // ping (fp16 features)
__device__ __half g_h1[N_NODES * OUT_F];       // pong (fp16 features)

// ---------------------------------------------------------------------------
// histogram of destination rows; 1 edge/thread
// ---------------------------------------------------------------------------
__global__ void hist_kernel(const int* __restrict__ ei) {
    int e = blockIdx.x * blockDim.x + threadIdx.x;
    if (e < N_EDGES) atomicAdd(&g_row_cnt[ei[e]], 1);
}

// ---------------------------------------------------------------------------
// scan phase 1: per-block (256 counters) partial sums  [196 blocks]
// Warp-shuffle reduce; 1 barrier.
// ---------------------------------------------------------------------------
__global__ void scan_partial_kernel() {
    __shared__ int pw[8];
    int t = threadIdx.x;
    int i = blockIdx.x * 256 + t;
    int lane = t & 31, w = t >> 5;

    int v = (i < N_NODES) ? g_row_cnt[i] : 0;
#pragma unroll
    for (int off = 16; off > 0; off >>= 1)
        v += __shfl_down_sync(0xffffffffu, v, off);
    if (lane == 0) pw[w] = v;
    __syncthreads();
    if (t == 0) {
        int s = 0;
#pragma unroll
        for (int j = 0; j < 8; j++) s += pw[j];
        g_part[blockIdx.x] = s;
    }
}

// ---------------------------------------------------------------------------
// scan phase 2 (fused): block offset = reduction over earlier partials,
// plus shuffle-based local exclusive scan -> row_ptr & scatter cursor.
// 2 barriers total.  [196 blocks]
// ---------------------------------------------------------------------------
__global__ void scan_apply_kernel() {
    __shared__ int warp_tot[8];
    __shared__ int warp_off[8];
    __shared__ int pw[8];
    __shared__ int s_blkoff;

    int t   = threadIdx.x;
    int bid = blockIdx.x;
    int i   = bid * 256 + t;
    int lane = t & 31, w = t >> 5;

    int c = (i < N_NODES) ? g_row_cnt[i] : 0;

    // inclusive warp scan of counters (shuffles, no smem)
    int v = c;
#pragma unroll
    for (int off = 1; off < 32; off <<= 1) {
        int n = __shfl_up_sync(0xffffffffu, v, off);
        if (lane >= off) v += n;
    }
    if (lane == 31) warp_tot[w] = v;

    // earlier-block partials: reduce across the block (values 0 where t>=bid)
    int p = (t < bid) ? g_part[t] : 0;   // bid <= 195 < 256, safe
#pragma unroll
    for (int off = 16; off > 0; off >>= 1)
        p += __shfl_down_sync(0xffffffffu, p, off);
    if (lane == 0) pw[w] = p;
    __syncthreads();

    if (w == 0) {
        // exclusive scan of 8 warp totals (in lanes 0..7)
        int wt = (lane < 8) ? warp_tot[lane] : 0;
        int ws = wt;
#pragma unroll
        for (int off = 1; off < 8; off <<= 1) {
            int n = __shfl_up_sync(0xffffffffu, ws, off);
            if (lane >= off) ws += n;
        }
        if (lane < 8) warp_off[lane] = ws - wt;
        // reduce the 8 per-warp partial sums -> block offset
        int bo = (lane < 8) ? pw[lane] : 0;
#pragma unroll
        for (int off = 4; off > 0; off >>= 1)
            bo += __shfl_down_sync(0xffffffffu, bo, off);
        if (lane == 0) s_blkoff = bo;
    }
    __syncthreads();

    int excl = (v - c) + warp_off[w] + s_blkoff;
    if (i < N_NODES) {
        g_row_ptr[i] = excl;
        g_row_cnt[i] = excl;   // scatter cursor
    }
    if (bid == 0 && t == 0) g_row_ptr[N_NODES] = N_EDGES;
}

// ---------------------------------------------------------------------------
// scatter edges into CSR order; 1 edge/thread.
// Stores col pre-scaled by 16 (uint2 index) to save an IMAD in spmm.
// ---------------------------------------------------------------------------
__global__ void scatter_kernel(const int* __restrict__ ei,
                               const float* __restrict__ attr) {
    int e = blockIdx.x * blockDim.x + threadIdx.x;
    if (e < N_EDGES) {
        int row = ei[e];
        int col = ei[N_EDGES + e];
        float a = attr[e];
        int pos = atomicAdd(&g_row_cnt[row], 1);
        g_edge_sorted[pos] = make_int2(col * 16, __float_as_int(a));
    }
}

// ---------------------------------------------------------------------------
// GEMM via tensor cores: out[n,o] = sum_k x[n,k] * W[o,k] + b[o]
// fp16 inputs (converted on the fly), fp32 accumulate, fp16 store.
// ---------------------------------------------------------------------------
__global__ __launch_bounds__(128)
void gemm_wmma_kernel(const float* __restrict__ x,
                      const float* __restrict__ W,
                      const float* __restrict__ b,
                      __half* __restrict__ out) {
    __shared__ __half Xs[64 * 128];
    __shared__ __half Wsh[64 * 128];

    int tid  = threadIdx.x;
    int warp = tid >> 5;
    int lane = tid & 31;
    int row0 = blockIdx.x * 64;

    for (int i = tid; i < 64 * 128 / 4; i += 128) {
        float4 v = __ldg((const float4*)W + i);
        __half2 h0 = __floats2half2_rn(v.x, v.y);
        __half2 h1 = __floats2half2_rn(v.z, v.w);
        ((__half2*)Wsh)[i * 2]     = h0;
        ((__half2*)Wsh)[i * 2 + 1] = h1;
    }
    for (int i = tid; i < 64 * 128 / 4; i += 128) {
        int r = i >> 5;
        int c = i & 31;
        int gr = row0 + r;
        if (gr >= N_NODES) gr = N_NODES - 1;
        float4 v = __ldg((const float4*)&x[gr * IN_F] + c);
        __half2 h0 = __floats2half2_rn(v.x, v.y);
        __half2 h1 = __floats2half2_rn(v.z, v.w);
        ((__half2*)Xs)[i * 2]     = h0;
        ((__half2*)Xs)[i * 2 + 1] = h1;
    }
    __syncthreads();

    wmma::fragment<wmma::accumulator, 16, 16, 16, float> acc[4];
#pragma unroll
    for (int j = 0; j < 4; j++) wmma::fill_fragment(acc[j], 0.0f);

#pragma unroll
    for (int k = 0; k < IN_F; k += 16) {
        wmma::fragment<wmma::matrix_a, 16, 16, 16, __half, wmma::row_major> af;
        wmma::load_matrix_sync(af, Xs + (warp * 16) * 128 + k, 128);
#pragma unroll
        for (int j = 0; j < 4; j++) {
            wmma::fragment<wmma::matrix_b, 16, 16, 16, __half, wmma::col_major> bf;
            wmma::load_matrix_sync(bf, Wsh + (j * 16) * 128 + k, 128);
            wmma::mma_sync(acc[j], af, bf, acc[j]);
        }
    }

    __syncthreads();
    float* stage = (float*)Xs;
    float* st = stage + warp * 16 * 64;
#pragma unroll
    for (int j = 0; j < 4; j++)
        wmma::store_matrix_sync(st + j * 16, acc[j], 64, wmma::mem_row_major);
    __syncwarp();

    for (int it = lane; it < 16 * 16; it += 32) {
        int r  = it >> 4;
        int c4 = it & 15;
        int gr = row0 + warp * 16 + r;
        if (gr < N_NODES) {
            float4 bias = __ldg((const float4*)b + c4);
            float v0 = st[r * 64 + c4 * 4 + 0] + bias.x;
            float v1 = st[r * 64 + c4 * 4 + 1] + bias.y;
            float v2 = st[r * 64 + c4 * 4 + 2] + bias.z;
            float v3 = st[r * 64 + c4 * 4 + 3] + bias.w;
            __half2 h0 = __floats2half2_rn(v0, v1);
            __half2 h1 = __floats2half2_rn(v2, v3);
            uint2 u;
            u.x = *(unsigned int*)&h0;
            u.y = *(unsigned int*)&h1;
            ((uint2*)out)[gr * 16 + c4] = u;
        }
    }
}

// ---------------------------------------------------------------------------
// SPMM (CSR): 2 rows/warp, 16 lanes/row, 4 fp16 feats per lane (8B gather).
// fp32 accumulate, unroll-4. FINAL=true writes fp32 to d_out, else fp16.
// Edge payload carries col*16 (pre-scaled uint2 index).
// (FROZEN: measured-best configuration, 107.8/106.5/106.4 us.)
// ---------------------------------------------------------------------------
template <bool FINAL>
__global__ __launch_bounds__(256, 8)
void spmm_kernel(const __half* __restrict__ in, void* __restrict__ outv) {
    int warp = (blockIdx.x * blockDim.x + threadIdx.x) >> 5;
    int lane = threadIdx.x & 31;
    int half_id = lane >> 4;
    int fl      = lane & 15;

    int row = warp * 2 + half_id;
    if (row >= N_NODES) return;

    int s = __ldg(&g_row_ptr[row]);
    int e = __ldg(&g_row_ptr[row + 1]);

    const uint2* inp = (const uint2*)in;
    float4 a0 = make_float4(0.f, 0.f, 0.f, 0.f);
    float4 a1 = make_float4(0.f, 0.f, 0.f, 0.f);
    float4 a2 = make_float4(0.f, 0.f, 0.f, 0.f);
    float4 a3 = make_float4(0.f, 0.f, 0.f, 0.f);

    int i = s;
    for (; i + 4 <= e; i += 4) {
        int2 e0 = __ldg(&g_edge_sorted[i]);
        int2 e1 = __ldg(&g_edge_sorted[i + 1]);
        int2 e2 = __ldg(&g_edge_sorted[i + 2]);
        int2 e3 = __ldg(&g_edge_sorted[i + 3]);
        uint2 v0 = __ldg(&inp[e0.x + fl]);
        uint2 v1 = __ldg(&inp[e1.x + fl]);
        uint2 v2 = __ldg(&inp[e2.x + fl]);
        uint2 v3 = __ldg(&inp[e3.x + fl]);
        float w0 = __int_as_float(e0.y);
        float w1 = __int_as_float(e1.y);
        float w2 = __int_as_float(e2.y);
        float w3 = __int_as_float(e3.y);

        float2 f;
        f = __half22float2(*(__half2*)&v0.x); a0.x += w0 * f.x; a0.y += w0 * f.y;
        f = __half22float2(*(__half2*)&v0.y); a0.z += w0 * f.x; a0.w += w0 * f.y;
        f = __half22float2(*(__half2*)&v1.x); a1.x += w1 * f.x; a1.y += w1 * f.y;
        f = __half22float2(*(__half2*)&v1.y); a1.z += w1 * f.x; a1.w += w1 * f.y;
        f = __half22float2(*(__half2*)&v2.x); a2.x += w2 * f.x; a2.y += w2 * f.y;
        f = __half22float2(*(__half2*)&v2.y); a2.z += w2 * f.x; a2.w += w2 * f.y;
        f = __half22float2(*(__half2*)&v3.x); a3.x += w3 * f.x; a3.y += w3 * f.y;
        f = __half22float2(*(__half2*)&v3.y); a3.z += w3 * f.x; a3.w += w3 * f.y;
    }
    for (; i < e; i++) {
        int2 ed = __ldg(&g_edge_sorted[i]);
        uint2 v = __ldg(&inp[ed.x + fl]);
        float w = __int_as_float(ed.y);
        float2 f;
        f = __half22float2(*(__half2*)&v.x); a0.x += w * f.x; a0.y += w * f.y;
        f = __half22float2(*(__half2*)&v.y); a0.z += w * f.x; a0.w += w * f.y;
    }

    float4 acc;
    acc.x = (a0.x + a1.x) + (a2.x + a3.x);
    acc.y = (a0.y + a1.y) + (a2.y + a3.y);
    acc.z = (a0.z + a1.z) + (a2.z + a3.z);
    acc.w = (a0.w + a1.w) + (a2.w + a3.w);

    if (FINAL) {
        ((float4*)outv)[row * 16 + fl] = acc;
    } else {
        __half2 h0 = __floats2half2_rn(acc.x, acc.y);
        __half2 h1 = __floats2half2_rn(acc.z, acc.w);
        uint2 st;
        st.x = *(unsigned int*)&h0;
        st.y = *(unsigned int*)&h1;
        ((uint2*)outv)[row * 16 + fl] = st;
    }
}

// ---------------------------------------------------------------------------
// launch: fork GEMM onto a side stream, overlapping with CSR build
// ---------------------------------------------------------------------------
extern "C" void kernel_launch(void* const* d_in, const int* in_sizes, int n_in,
                              void* d_out, int out_size) {
    const float* x    = (const float*)d_in[0];
    const int*   ei   = (const int*)d_in[1];   // int32 (JAX x64 disabled)
    const float* attr = (const float*)d_in[2];
    const float* W    = (const float*)d_in[3];
    const float* b    = (const float*)d_in[4];
    float*       out  = (float*)d_out;

    __half *h0, *h1;
    int    *cnt;
    cudaGetSymbolAddress((void**)&h0,  g_h0);
    cudaGetSymbolAddress((void**)&h1,  g_h1);
    cudaGetSymbolAddress((void**)&cnt, g_row_cnt);

    // Fork side stream for the independent GEMM.
    cudaStream_t s2;
    cudaStreamCreateWithFlags(&s2, cudaStreamNonBlocking);
    cudaEvent_t ev_fork, ev_join;
    cudaEventCreateWithFlags(&ev_fork, cudaEventDisableTiming);
    cudaEventCreateWithFlags(&ev_join, cudaEventDisableTiming);

    cudaEventRecord(ev_fork, 0);
    cudaStreamWaitEvent(s2, ev_fork, 0);

    gemm_wmma_kernel<<<(N_NODES + 63) / 64, 128, 0, s2>>>(x, W, b, h0);
    cudaEventRecord(ev_join, s2);

    // Main stream: CSR build (scan = 2 full-chip phases, shuffle-based)
    cudaMemsetAsync(cnt, 0, N_NODES * sizeof(int), 0);
    hist_kernel<<<(N_EDGES + 255) / 256, 256>>>(ei);
    scan_partial_kernel<<<NBLK_SCAN, 256>>>();
    scan_apply_kernel<<<NBLK_SCAN, 256>>>();
    scatter_kernel<<<(N_EDGES + 255) / 256, 256>>>(ei, attr);

    cudaStreamWaitEvent(0, ev_join, 0);

    // 3 SPMM rounds: h0 -> h1 -> h0 -> d_out (fp32); 2 rows per warp
    int blocks = (N_NODES / 2 * 32 + 255) / 256;
    spmm_kernel<false><<<blocks, 256>>>(h0, h1);
    spmm_kernel<false><<<blocks, 256>>>(h1, h0);
    spmm_kernel<true ><<<blocks, 256>>>(h0, out);
}